// round 1
// baseline (speedup 1.0000x reference)
#include <cuda_runtime.h>
#include <math.h>

// Problem shape (fixed by setup_inputs): B=8, Sq=Sk=1024, D=64, N_QUBITS=4.
#define B_     8
#define SQ_    1024
#define SK_    1024
#define D_     64
#define NQ_    4
#define NROWS_ (B_ * SQ_)          // 8192 rows per side

// Scratch: Bloch vectors, 12 floats per row (4 qubits x 3 components).
// q-side is pre-scaled by 0.5 so per-qubit factor = 0.5 + dot3(rq', rk).
__device__ float g_rq[NROWS_ * 12];
__device__ float g_rk[NROWS_ * 12];

// ---------------------------------------------------------------------------
// Phase 1: per-row Bloch vectors.  rows [0,8192) -> query, [8192,16384) -> key
// ---------------------------------------------------------------------------
__global__ void bloch_kernel(const float* __restrict__ query,
                             const float* __restrict__ key,
                             const float* __restrict__ theta_q,
                             const float* __restrict__ theta_k)
{
    int row = blockIdx.x * blockDim.x + threadIdx.x;
    if (row >= 2 * NROWS_) return;

    bool isQ = row < NROWS_;
    int r = isQ ? row : row - NROWS_;
    const float* src = isQ ? query : key;
    const float* th  = isQ ? theta_q : theta_k;
    float* dst       = isQ ? g_rq : g_rk;
    float scale      = isQ ? 0.5f : 1.0f;

    const float* x = src + (size_t)r * D_;
    float out[12];

#pragma unroll
    for (int n = 0; n < NQ_; n++) {
        // a = tanh(x) * pi/2 ; c = cos a, s = sin a
        float a = tanhf(x[n]) * 1.5707963267948966f;
        float s, c;
        sincosf(a, &s, &c);

        float phi = th[n * 3 + 0];
        float t2  = th[n * 3 + 1] * 0.5f;
        float om  = th[n * 3 + 2];
        float st, ct;
        sincosf(t2, &st, &ct);
        float al = 0.5f * (phi + om);
        float be = 0.5f * (phi - om);
        float sa, ca, sb, cb;
        sincosf(al, &sa, &ca);
        sincosf(be, &sb, &cb);

        // v0 = ct*c*e^{-i al} - st*s*e^{+i be}
        // v1 = st*c*e^{-i be} + ct*s*e^{+i al}
        float A  = ct * c, Bv = st * s, C = st * c, Dv = ct * s;
        float v0r =  A * ca - Bv * cb;
        float v0i = -A * sa - Bv * sb;
        float v1r =  C * cb + Dv * ca;
        float v1i = -C * sb + Dv * sa;

        // Bloch vector of |v><v|
        float rx = 2.0f * (v0r * v1r + v0i * v1i);
        float ry = 2.0f * (v0r * v1i - v0i * v1r);
        float rz = v0r * v0r + v0i * v0i - v1r * v1r - v1i * v1i;

        out[n * 3 + 0] = rx * scale;
        out[n * 3 + 1] = ry * scale;
        out[n * 3 + 2] = rz * scale;
    }

    float* d = dst + (size_t)r * 12;
#pragma unroll
    for (int j = 0; j < 12; j += 4)
        *(float4*)(d + j) = *(const float4*)(out + j);
}

// ---------------------------------------------------------------------------
// Phase 2: out[b][q][k] = 0.5 + 0.5 * prod_n (0.5 + rq'[n].rk[n])
// Tile: 32 q-rows x 128 k-cols per block, 256 threads, each thread computes a
// 4x4 micro-tile and writes 4x STG.128.  Pure store-bandwidth bound.
// ---------------------------------------------------------------------------
#define TQ 32
#define TK 128

__global__ __launch_bounds__(256) void pair_kernel(float* __restrict__ out)
{
    __shared__ float sq[TQ * 12];
    __shared__ float sk[TK * 12];

    int b  = blockIdx.z;
    int q0 = blockIdx.y * TQ;
    int k0 = blockIdx.x * TK;
    int tid = threadIdx.x;

    const float4* gq = (const float4*)(g_rq + (size_t)(b * SQ_ + q0) * 12);
    const float4* gk = (const float4*)(g_rk + (size_t)(b * SK_ + k0) * 12);

    // TQ*12 floats = 96 float4 ; TK*12 floats = 384 float4
    if (tid < 96) ((float4*)sq)[tid] = gq[tid];
#pragma unroll
    for (int i = tid; i < 384; i += 256) ((float4*)sk)[i] = gk[i];
    __syncthreads();

    int k4 = tid & 31;   // float4 group along k : cols k4*4 .. +3
    int qg = tid >> 5;   // q group: rows qg*4 .. +3

    // cache this thread's 4 k-columns in registers
    float kd[4][12];
#pragma unroll
    for (int c = 0; c < 4; c++) {
        int kr = k4 * 4 + c;
#pragma unroll
        for (int j = 0; j < 12; j += 4)
            *(float4*)&kd[c][j] = *(const float4*)&sk[kr * 12 + j];
    }

#pragma unroll
    for (int r = 0; r < 4; r++) {
        int qr = qg * 4 + r;
        float qd[12];
#pragma unroll
        for (int j = 0; j < 12; j += 4)
            *(float4*)&qd[j] = *(const float4*)&sq[qr * 12 + j];

        float4 res;
        float* resp = &res.x;
#pragma unroll
        for (int c = 0; c < 4; c++) {
            float f = 1.0f;
#pragma unroll
            for (int n = 0; n < NQ_; n++) {
                float t = 0.5f;
                t = fmaf(qd[n * 3 + 0], kd[c][n * 3 + 0], t);
                t = fmaf(qd[n * 3 + 1], kd[c][n * 3 + 1], t);
                t = fmaf(qd[n * 3 + 2], kd[c][n * 3 + 2], t);
                f *= t;
            }
            resp[c] = fmaf(0.5f, f, 0.5f);
        }

        size_t oidx = ((size_t)(b * SQ_ + q0 + qr) * SK_) + k0 + k4 * 4;
        *(float4*)(out + oidx) = res;
    }
}

extern "C" void kernel_launch(void* const* d_in, const int* in_sizes, int n_in,
                              void* d_out, int out_size)
{
    const float* query   = (const float*)d_in[0];
    const float* key     = (const float*)d_in[1];
    const float* theta_q = (const float*)d_in[2];
    const float* theta_k = (const float*)d_in[3];
    float* out = (float*)d_out;

    bloch_kernel<<<(2 * NROWS_ + 255) / 256, 256>>>(query, key, theta_q, theta_k);

    dim3 grid(SK_ / TK, SQ_ / TQ, B_);
    pair_kernel<<<grid, 256>>>(out);
}

// round 2
// speedup vs baseline: 1.4524x; 1.4524x over previous
#include <cuda_runtime.h>
#include <math.h>

// Problem shape (fixed by setup_inputs): B=8, Sq=Sk=1024, D=64, N_QUBITS=4.
#define B_     8
#define SQ_    1024
#define SK_    1024
#define D_     64
#define NQ_    4
#define NROWS_ (B_ * SQ_)          // 8192 rows per side

// Scratch Bloch vectors.
//  q-side: AoS  [row][12]          (warp-uniform broadcast reads)
//  k-side: SoA  [b][comp(12)][SK]  (vectorized conflict-free reads)
// q-side is pre-scaled by 0.5 so per-qubit factor = 0.5 + dot3(rq', rk).
__device__ float g_rq[NROWS_ * 12];
__device__ float g_rk[B_ * 12 * SK_];

// ---------------------------------------------------------------------------
// Phase 1: per-row Bloch vectors.  rows [0,8192) -> query, [8192,16384) -> key
// ---------------------------------------------------------------------------
__global__ void bloch_kernel(const float* __restrict__ query,
                             const float* __restrict__ key,
                             const float* __restrict__ theta_q,
                             const float* __restrict__ theta_k)
{
    int row = blockIdx.x * blockDim.x + threadIdx.x;
    if (row >= 2 * NROWS_) return;

    bool isQ = row < NROWS_;
    int r = isQ ? row : row - NROWS_;
    const float* src = isQ ? query : key;
    const float* th  = isQ ? theta_q : theta_k;
    float scale      = isQ ? 0.5f : 1.0f;

    const float* x = src + (size_t)r * D_;
    float out[12];

#pragma unroll
    for (int n = 0; n < NQ_; n++) {
        // a = tanh(x) * pi/2 ; c = cos a, s = sin a
        float a = tanhf(x[n]) * 1.5707963267948966f;
        float s, c;
        sincosf(a, &s, &c);

        float phi = th[n * 3 + 0];
        float t2  = th[n * 3 + 1] * 0.5f;
        float om  = th[n * 3 + 2];
        float st, ct;
        sincosf(t2, &st, &ct);
        float al = 0.5f * (phi + om);
        float be = 0.5f * (phi - om);
        float sa, ca, sb, cb;
        sincosf(al, &sa, &ca);
        sincosf(be, &sb, &cb);

        // v0 = ct*c*e^{-i al} - st*s*e^{+i be}
        // v1 = st*c*e^{-i be} + ct*s*e^{+i al}
        float A  = ct * c, Bv = st * s, C = st * c, Dv = ct * s;
        float v0r =  A * ca - Bv * cb;
        float v0i = -A * sa - Bv * sb;
        float v1r =  C * cb + Dv * ca;
        float v1i = -C * sb + Dv * sa;

        // Bloch vector of |v><v|
        float rx = 2.0f * (v0r * v1r + v0i * v1i);
        float ry = 2.0f * (v0r * v1i - v0i * v1r);
        float rz = v0r * v0r + v0i * v0i - v1r * v1r - v1i * v1i;

        out[n * 3 + 0] = rx * scale;
        out[n * 3 + 1] = ry * scale;
        out[n * 3 + 2] = rz * scale;
    }

    if (isQ) {
        float* d = g_rq + (size_t)r * 12;
#pragma unroll
        for (int j = 0; j < 12; j += 4)
            *(float4*)(d + j) = *(const float4*)(out + j);
    } else {
        int b = r >> 10;           // SK_ = 1024
        int s = r & (SK_ - 1);
#pragma unroll
        for (int j = 0; j < 12; j++)
            g_rk[((size_t)(b * 12 + j)) * SK_ + s] = out[j];
    }
}

// ---------------------------------------------------------------------------
// Phase 2: out[b][q][k] = 0.5 + 0.5 * prod_n (0.5 + rq'[n].rk[n])
// Tile: 64 q-rows x 128 k-cols, 256 threads. Each thread holds 4 k-columns
// (SoA, 12 float4 regs) and iterates 8 q-rows -> 8 STG.128.
// k loads conflict-free; q loads warp-uniform broadcast.
// ---------------------------------------------------------------------------
#define TQ 64
#define TK 128

__global__ __launch_bounds__(256) void pair_kernel(float* __restrict__ out)
{
    __shared__ float4 skv[12][TK / 4];     // [component][k-float4]
    __shared__ float  sq[TQ * 12];         // AoS rows

    int b  = blockIdx.z;
    int q0 = blockIdx.y * TQ;
    int k0 = blockIdx.x * TK;
    int tid = threadIdx.x;

    // fill sq: TQ*12 floats = 192 float4
    if (tid < 192)
        ((float4*)sq)[tid] =
            ((const float4*)(g_rq + (size_t)(b * SQ_ + q0) * 12))[tid];

    // fill skv: 12 comps * 32 float4 = 384 float4, from SoA global
    {
        int i = tid;                       // first 256
        int comp = i >> 5, off = i & 31;
        skv[comp][off] =
            *(const float4*)(g_rk + ((size_t)(b * 12 + comp)) * SK_ + k0 + off * 4);
        i = tid + 256;                     // remaining 128
        if (tid < 128) {
            comp = i >> 5; off = i & 31;
            skv[comp][off] =
                *(const float4*)(g_rk + ((size_t)(b * 12 + comp)) * SK_ + k0 + off * 4);
        }
    }
    __syncthreads();

    int k4 = tid & 31;     // this thread's k-float4 (4 consecutive k columns)
    int qg = tid >> 5;     // q group: rows qg*8 .. qg*8+7

    // 12 components x 4 k-columns, register resident
    float4 kd[12];
#pragma unroll
    for (int j = 0; j < 12; j++) kd[j] = skv[j][k4];

    float* obase = out + ((size_t)(b * SQ_ + q0 + qg * 8) * SK_) + k0 + k4 * 4;

#pragma unroll
    for (int r = 0; r < 8; r++) {
        const float* qd = &sq[(qg * 8 + r) * 12];   // warp-uniform -> broadcast

        float4 prod = make_float4(1.f, 1.f, 1.f, 1.f);
#pragma unroll
        for (int n = 0; n < NQ_; n++) {
            float qx = qd[3 * n + 0];
            float qy = qd[3 * n + 1];
            float qz = qd[3 * n + 2];
            float4 kx = kd[3 * n + 0];
            float4 ky = kd[3 * n + 1];
            float4 kz = kd[3 * n + 2];
            float4 t;
            t.x = fmaf(qx, kx.x, fmaf(qy, ky.x, fmaf(qz, kz.x, 0.5f)));
            t.y = fmaf(qx, kx.y, fmaf(qy, ky.y, fmaf(qz, kz.y, 0.5f)));
            t.z = fmaf(qx, kx.z, fmaf(qy, ky.z, fmaf(qz, kz.z, 0.5f)));
            t.w = fmaf(qx, kx.w, fmaf(qy, ky.w, fmaf(qz, kz.w, 0.5f)));
            prod.x *= t.x; prod.y *= t.y; prod.z *= t.z; prod.w *= t.w;
        }
        float4 res;
        res.x = fmaf(0.5f, prod.x, 0.5f);
        res.y = fmaf(0.5f, prod.y, 0.5f);
        res.z = fmaf(0.5f, prod.z, 0.5f);
        res.w = fmaf(0.5f, prod.w, 0.5f);

        *(float4*)(obase + (size_t)r * SK_) = res;
    }
}

extern "C" void kernel_launch(void* const* d_in, const int* in_sizes, int n_in,
                              void* d_out, int out_size)
{
    const float* query   = (const float*)d_in[0];
    const float* key     = (const float*)d_in[1];
    const float* theta_q = (const float*)d_in[2];
    const float* theta_k = (const float*)d_in[3];
    float* out = (float*)d_out;

    bloch_kernel<<<(2 * NROWS_ + 255) / 256, 256>>>(query, key, theta_q, theta_k);

    dim3 grid(SK_ / TK, SQ_ / TQ, B_);
    pair_kernel<<<grid, 256>>>(out);
}

// round 3
// speedup vs baseline: 1.5458x; 1.0643x over previous
#include <cuda_runtime.h>
#include <math.h>

// Problem shape (fixed by setup_inputs): B=8, Sq=Sk=1024, D=64, N_QUBITS=4.
#define B_     8
#define SQ_    1024
#define SK_    1024
#define D_     64
#define NQ_    4
#define NROWS_ (B_ * SQ_)          // 8192 rows per side

// Scratch Bloch vectors.
//  q-side: AoS  [row][12]          (loaded broadcast, duplicated into smem)
//  k-side: SoA  [b][comp(12)][SK]  (vectorized conflict-free reads)
// q-side is pre-scaled by 0.5 so per-qubit factor = 0.5 + dot3(rq', rk).
__device__ float g_rq[NROWS_ * 12];
__device__ float g_rk[B_ * 12 * SK_];

// ---------------------------------------------------------------------------
// packed f32x2 helpers (Blackwell: fma.rn.f32x2 / mul.rn.f32x2)
// ---------------------------------------------------------------------------
__device__ __forceinline__ unsigned long long f2fma(unsigned long long a,
                                                    unsigned long long b,
                                                    unsigned long long c)
{
    unsigned long long d;
    asm("fma.rn.f32x2 %0, %1, %2, %3;" : "=l"(d) : "l"(a), "l"(b), "l"(c));
    return d;
}
__device__ __forceinline__ unsigned long long f2mul(unsigned long long a,
                                                    unsigned long long b)
{
    unsigned long long d;
    asm("mul.rn.f32x2 %0, %1, %2;" : "=l"(d) : "l"(a), "l"(b));
    return d;
}

#define HALF2_ 0x3F0000003F000000ULL   // {0.5f, 0.5f}
#define ONE2_  0x3F8000003F800000ULL   // {1.0f, 1.0f}

// ---------------------------------------------------------------------------
// Phase 1: per-row Bloch vectors.  rows [0,8192) -> query, [8192,16384) -> key
// ---------------------------------------------------------------------------
__global__ void bloch_kernel(const float* __restrict__ query,
                             const float* __restrict__ key,
                             const float* __restrict__ theta_q,
                             const float* __restrict__ theta_k)
{
    int row = blockIdx.x * blockDim.x + threadIdx.x;
    if (row >= 2 * NROWS_) return;

    bool isQ = row < NROWS_;
    int r = isQ ? row : row - NROWS_;
    const float* src = isQ ? query : key;
    const float* th  = isQ ? theta_q : theta_k;
    float scale      = isQ ? 0.5f : 1.0f;

    const float* x = src + (size_t)r * D_;
    float out[12];

#pragma unroll
    for (int n = 0; n < NQ_; n++) {
        float a = tanhf(x[n]) * 1.5707963267948966f;
        float s, c;
        sincosf(a, &s, &c);

        float phi = th[n * 3 + 0];
        float t2  = th[n * 3 + 1] * 0.5f;
        float om  = th[n * 3 + 2];
        float st, ct;
        sincosf(t2, &st, &ct);
        float al = 0.5f * (phi + om);
        float be = 0.5f * (phi - om);
        float sa, ca, sb, cb;
        sincosf(al, &sa, &ca);
        sincosf(be, &sb, &cb);

        float A  = ct * c, Bv = st * s, C = st * c, Dv = ct * s;
        float v0r =  A * ca - Bv * cb;
        float v0i = -A * sa - Bv * sb;
        float v1r =  C * cb + Dv * ca;
        float v1i = -C * sb + Dv * sa;

        float rx = 2.0f * (v0r * v1r + v0i * v1i);
        float ry = 2.0f * (v0r * v1i - v0i * v1r);
        float rz = v0r * v0r + v0i * v0i - v1r * v1r - v1i * v1i;

        out[n * 3 + 0] = rx * scale;
        out[n * 3 + 1] = ry * scale;
        out[n * 3 + 2] = rz * scale;
    }

    if (isQ) {
        float* d = g_rq + (size_t)r * 12;
#pragma unroll
        for (int j = 0; j < 12; j += 4)
            *(float4*)(d + j) = *(const float4*)(out + j);
    } else {
        int b = r >> 10;           // SK_ = 1024
        int s = r & (SK_ - 1);
#pragma unroll
        for (int j = 0; j < 12; j++)
            g_rk[((size_t)(b * 12 + j)) * SK_ + s] = out[j];
    }
}

// ---------------------------------------------------------------------------
// Phase 2: out[b][q][k] = 0.5 + 0.5 * prod_n (0.5 + rq'[n].rk[n])
// Tile: 128 q-rows x 128 k-cols, 256 threads.  Each thread owns 4 k-columns
// as 2 packed f32x2 pairs (register resident) and iterates 16 q-rows.
// All inner-loop math is fma.rn.f32x2 / mul.rn.f32x2 (2 lanes per instr).
// q rows live in smem PRE-DUPLICATED ({v,v} pairs) so one LDS yields a
// ready packed operand — no per-element duplication movs.
// ---------------------------------------------------------------------------
#define TQ 128
#define TK 128

__global__ __launch_bounds__(256) void pair_kernel(float* __restrict__ out)
{
    __shared__ __align__(16) float  sqd[TQ][24];       // duplicated q pairs
    __shared__ __align__(16) float4 skv[12][TK / 4];   // SoA k tile

    int b  = blockIdx.z;
    int q0 = blockIdx.y * TQ;
    int k0 = blockIdx.x * TK;
    int tid = threadIdx.x;

    // fill skv: 12 comps * 32 float4 = 384 float4
#pragma unroll
    for (int i = tid; i < 384; i += 256) {
        int comp = i >> 5, off = i & 31;
        skv[comp][off] =
            *(const float4*)(g_rk + ((size_t)(b * 12 + comp)) * SK_ + k0 + off * 4);
    }
    // fill sqd: TQ*12 scalars, duplicated into pairs
#pragma unroll
    for (int i = tid; i < TQ * 12; i += 256) {
        int row = i / 12, comp = i - row * 12;
        float v = g_rq[(size_t)(b * SQ_ + q0 + row) * 12 + comp];
        *(float2*)&sqd[row][comp * 2] = make_float2(v, v);
    }
    __syncthreads();

    int k4 = tid & 31;     // this thread's 4 consecutive k columns
    int qg = tid >> 5;     // q group: rows qg*16 .. qg*16+15

    // k tile: 12 components x (2 packed pairs) in registers
    ulonglong2 kd[12];
#pragma unroll
    for (int j = 0; j < 12; j++)
        kd[j] = *(const ulonglong2*)&skv[j][k4];

    float* obase = out + ((size_t)(b * SQ_ + q0 + qg * 16) * SK_) + k0 + k4 * 4;

#pragma unroll
    for (int r = 0; r < 16; r++) {
        // 6 LDS.128 -> 12 packed q components (warp-uniform broadcast)
        unsigned long long qd[12];
        const ulonglong2* qrow = (const ulonglong2*)&sqd[qg * 16 + r][0];
#pragma unroll
        for (int j = 0; j < 6; j++) {
            ulonglong2 v = qrow[j];
            qd[2 * j]     = v.x;
            qd[2 * j + 1] = v.y;
        }

        unsigned long long p0 = ONE2_, p1 = ONE2_;
#pragma unroll
        for (int n = 0; n < NQ_; n++) {
            unsigned long long qx = qd[3 * n + 0];
            unsigned long long qy = qd[3 * n + 1];
            unsigned long long qz = qd[3 * n + 2];
            unsigned long long t0 =
                f2fma(qx, kd[3 * n + 0].x,
                f2fma(qy, kd[3 * n + 1].x,
                f2fma(qz, kd[3 * n + 2].x, HALF2_)));
            unsigned long long t1 =
                f2fma(qx, kd[3 * n + 0].y,
                f2fma(qy, kd[3 * n + 1].y,
                f2fma(qz, kd[3 * n + 2].y, HALF2_)));
            p0 = f2mul(p0, t0);
            p1 = f2mul(p1, t1);
        }
        p0 = f2fma(p0, HALF2_, HALF2_);
        p1 = f2fma(p1, HALF2_, HALF2_);

        asm volatile("st.global.v2.b64 [%0], {%1, %2};"
                     :: "l"(obase + (size_t)r * SK_), "l"(p0), "l"(p1)
                     : "memory");
    }
}

extern "C" void kernel_launch(void* const* d_in, const int* in_sizes, int n_in,
                              void* d_out, int out_size)
{
    const float* query   = (const float*)d_in[0];
    const float* key     = (const float*)d_in[1];
    const float* theta_q = (const float*)d_in[2];
    const float* theta_k = (const float*)d_in[3];
    float* out = (float*)d_out;

    bloch_kernel<<<(2 * NROWS_ + 255) / 256, 256>>>(query, key, theta_q, theta_k);

    dim3 grid(SK_ / TK, SQ_ / TQ, B_);
    pair_kernel<<<grid, 256>>>(out);
}

// round 4
// speedup vs baseline: 1.7314x; 1.1201x over previous
#include <cuda_runtime.h>
#include <math.h>

// Problem shape (fixed by setup_inputs): B=8, Sq=Sk=1024, D=64, N_QUBITS=4.
#define B_     8
#define SQ_    1024
#define SK_    1024
#define D_     64
#define NQ_    4
#define NROWS_ (B_ * SQ_)          // 8192 rows per side

// Rank-reduced scratch:
//  q-side AoS [row][8]:  per qubit (0.5*sin(pi t), 0.5*cos(pi t))
//  k-side SoA [b][comp(8)][SK]: per qubit (G00*Sk+G01*Ck, G10*Sk+G11*Ck)
// so per-qubit factor = 0.5 + q0*k0 + q1*k1.
__device__ float g_q[NROWS_ * 8];
__device__ float g_k[B_ * 8 * SK_];

// ---------------------------------------------------------------------------
// packed f32x2 helpers
// ---------------------------------------------------------------------------
__device__ __forceinline__ unsigned long long f2fma(unsigned long long a,
                                                    unsigned long long b,
                                                    unsigned long long c)
{
    unsigned long long d;
    asm("fma.rn.f32x2 %0, %1, %2, %3;" : "=l"(d) : "l"(a), "l"(b), "l"(c));
    return d;
}
__device__ __forceinline__ unsigned long long f2mul(unsigned long long a,
                                                    unsigned long long b)
{
    unsigned long long d;
    asm("mul.rn.f32x2 %0, %1, %2;" : "=l"(d) : "l"(a), "l"(b));
    return d;
}

#define HALF2_ 0x3F0000003F000000ULL   // {0.5f, 0.5f}

// Bloch-rotation columns of M = Rz(om)*Ry(th)*Rz(phi):
//   u = M*ex, v = M*ez
__device__ __forceinline__ void uv_cols(float phi, float th, float om,
                                        float u[3], float v[3])
{
    float sp, cp, st, ct, so, co;
    sincosf(phi, &sp, &cp);
    sincosf(th,  &st, &ct);
    sincosf(om,  &so, &co);
    // ex -> Rz(phi): (cp, sp, 0) -> Ry(th): (ct*cp, sp, -st*cp) -> Rz(om)
    float ax = ct * cp, ay = sp, az = -st * cp;
    u[0] = ax * co - ay * so;
    u[1] = ax * so + ay * co;
    u[2] = az;
    // ez -> Ry(th): (st, 0, ct) -> Rz(om)
    v[0] = st * co;
    v[1] = st * so;
    v[2] = ct;
}

// ---------------------------------------------------------------------------
// Phase 1: rows [0,8192) -> query side, [8192,16384) -> key side
// ---------------------------------------------------------------------------
__global__ void prep_kernel(const float* __restrict__ query,
                            const float* __restrict__ key,
                            const float* __restrict__ theta_q,
                            const float* __restrict__ theta_k)
{
    int row = blockIdx.x * blockDim.x + threadIdx.x;
    if (row >= 2 * NROWS_) return;

    bool isQ = row < NROWS_;
    int r = isQ ? row : row - NROWS_;
    const float* x = (isQ ? query : key) + (size_t)r * D_;

    // S,C per qubit
    float S[NQ_], C[NQ_];
#pragma unroll
    for (int n = 0; n < NQ_; n++) {
        float t = tanhf(x[n]);
        sincospif(t, &S[n], &C[n]);
    }

    if (isQ) {
        float out8[8];
#pragma unroll
        for (int n = 0; n < NQ_; n++) {
            out8[2 * n]     = 0.5f * S[n];
            out8[2 * n + 1] = 0.5f * C[n];
        }
        float* d = g_q + (size_t)r * 8;
        *(float4*)(d)     = *(const float4*)(out8);
        *(float4*)(d + 4) = *(const float4*)(out8 + 4);
    } else {
        int b = r >> 10;           // SK_ = 1024
        int s = r & (SK_ - 1);
#pragma unroll
        for (int n = 0; n < NQ_; n++) {
            float uq[3], vq[3], uk[3], vk[3];
            uv_cols(theta_q[3 * n], theta_q[3 * n + 1], theta_q[3 * n + 2], uq, vq);
            uv_cols(theta_k[3 * n], theta_k[3 * n + 1], theta_k[3 * n + 2], uk, vk);
            float G00 = uq[0] * uk[0] + uq[1] * uk[1] + uq[2] * uk[2];
            float G01 = uq[0] * vk[0] + uq[1] * vk[1] + uq[2] * vk[2];
            float G10 = vq[0] * uk[0] + vq[1] * uk[1] + vq[2] * uk[2];
            float G11 = vq[0] * vk[0] + vq[1] * vk[1] + vq[2] * vk[2];
            float k0 = G00 * S[n] + G01 * C[n];
            float k1 = G10 * S[n] + G11 * C[n];
            g_k[((size_t)(b * 8 + 2 * n))     * SK_ + s] = k0;
            g_k[((size_t)(b * 8 + 2 * n + 1)) * SK_ + s] = k1;
        }
    }
}

// ---------------------------------------------------------------------------
// Phase 2: out[b][q][k] = 0.5 + 0.5 * prod_n (0.5 + q0*k0 + q1*k1)
// Tile: 128 q-rows x 128 k-cols, 256 threads.  Each thread owns 4 k-columns
// as 2 packed f32x2 pairs per component (8 comps, register resident) and
// iterates 16 q-rows.  q rows live in smem PRE-DUPLICATED ({v,v} pairs).
// ---------------------------------------------------------------------------
#define TQ 128
#define TK 128

__global__ __launch_bounds__(256) void pair_kernel(float* __restrict__ out)
{
    __shared__ __align__(16) float  sqd[TQ][16];       // duplicated q pairs
    __shared__ __align__(16) float4 skv[8][TK / 4];    // SoA k tile

    int b  = blockIdx.z;
    int q0 = blockIdx.y * TQ;
    int k0 = blockIdx.x * TK;
    int tid = threadIdx.x;

    // fill skv: 8 comps * 32 float4 = 256 float4 -> one per thread
    {
        int comp = tid >> 5, off = tid & 31;
        skv[comp][off] =
            *(const float4*)(g_k + ((size_t)(b * 8 + comp)) * SK_ + k0 + off * 4);
    }
    // fill sqd: TQ*8 = 1024 scalars, duplicated into pairs
#pragma unroll
    for (int i = tid; i < TQ * 8; i += 256) {
        int row = i >> 3, comp = i & 7;
        float v = g_q[(size_t)(b * SQ_ + q0 + row) * 8 + comp];
        *(float2*)&sqd[row][comp * 2] = make_float2(v, v);
    }
    __syncthreads();

    int k4 = tid & 31;     // this thread's 4 consecutive k columns
    int qg = tid >> 5;     // q group: rows qg*16 .. qg*16+15

    // k tile: 8 components x (2 packed pairs) in registers
    ulonglong2 kd[8];
#pragma unroll
    for (int j = 0; j < 8; j++)
        kd[j] = *(const ulonglong2*)&skv[j][k4];

    float* obase = out + ((size_t)(b * SQ_ + q0 + qg * 16) * SK_) + k0 + k4 * 4;

#pragma unroll
    for (int r = 0; r < 16; r++) {
        // 4 LDS.128 -> 8 packed q components (warp-uniform broadcast)
        unsigned long long qd[8];
        const ulonglong2* qrow = (const ulonglong2*)&sqd[qg * 16 + r][0];
#pragma unroll
        for (int j = 0; j < 4; j++) {
            ulonglong2 v = qrow[j];
            qd[2 * j]     = v.x;
            qd[2 * j + 1] = v.y;
        }

        // per-qubit factors, product as a tree (short dep chain)
        unsigned long long t0[NQ_], t1[NQ_];
#pragma unroll
        for (int n = 0; n < NQ_; n++) {
            t0[n] = f2fma(qd[2 * n], kd[2 * n].x,
                    f2fma(qd[2 * n + 1], kd[2 * n + 1].x, HALF2_));
            t1[n] = f2fma(qd[2 * n], kd[2 * n].y,
                    f2fma(qd[2 * n + 1], kd[2 * n + 1].y, HALF2_));
        }
        unsigned long long p0 = f2mul(f2mul(t0[0], t0[1]), f2mul(t0[2], t0[3]));
        unsigned long long p1 = f2mul(f2mul(t1[0], t1[1]), f2mul(t1[2], t1[3]));
        p0 = f2fma(p0, HALF2_, HALF2_);
        p1 = f2fma(p1, HALF2_, HALF2_);

        asm volatile("st.global.v2.b64 [%0], {%1, %2};"
                     :: "l"(obase + (size_t)r * SK_), "l"(p0), "l"(p1)
                     : "memory");
    }
}

extern "C" void kernel_launch(void* const* d_in, const int* in_sizes, int n_in,
                              void* d_out, int out_size)
{
    const float* query   = (const float*)d_in[0];
    const float* key     = (const float*)d_in[1];
    const float* theta_q = (const float*)d_in[2];
    const float* theta_k = (const float*)d_in[3];
    float* out = (float*)d_out;

    prep_kernel<<<(2 * NROWS_ + 255) / 256, 256>>>(query, key, theta_q, theta_k);

    dim3 grid(SK_ / TK, SQ_ / TQ, B_);
    pair_kernel<<<grid, 256>>>(out);
}

// round 5
// speedup vs baseline: 1.8971x; 1.0957x over previous
#include <cuda_runtime.h>
#include <math.h>

// Problem shape (fixed by setup_inputs): B=8, Sq=Sk=1024, D=64, N_QUBITS=4.
#define B_     8
#define SQ_    1024
#define SK_    1024
#define D_     64
#define NQ_    4
#define NROWS_ (B_ * SQ_)          // 8192 rows per side

// Raw per-row scratch (NO theta dependence):
//  q-side AoS [row][8]:  per qubit (0.5*sin(pi t), 0.5*cos(pi t))
//  k-side SoA [b][comp(8)][SK]: per qubit (sin(pi t), cos(pi t))
// The theta-dependent 2x2 Gram matrix G per qubit is applied inside
// pair_kernel (block-scope, negligible), so per-qubit factor becomes
//   0.5 + q0*(G00 kS + G01 kC) + q1*(G10 kS + G11 kC).
__device__ float g_q[NROWS_ * 8];
__device__ float g_k[B_ * 8 * SK_];

// ---------------------------------------------------------------------------
// packed f32x2 helpers
// ---------------------------------------------------------------------------
__device__ __forceinline__ unsigned long long f2fma(unsigned long long a,
                                                    unsigned long long b,
                                                    unsigned long long c)
{
    unsigned long long d;
    asm("fma.rn.f32x2 %0, %1, %2, %3;" : "=l"(d) : "l"(a), "l"(b), "l"(c));
    return d;
}
__device__ __forceinline__ unsigned long long f2mul(unsigned long long a,
                                                    unsigned long long b)
{
    unsigned long long d;
    asm("mul.rn.f32x2 %0, %1, %2;" : "=l"(d) : "l"(a), "l"(b));
    return d;
}

#define HALF2_ 0x3F0000003F000000ULL   // {0.5f, 0.5f}

// Bloch-rotation columns of M = Rz(om)*Ry(th)*Rz(phi):  u = M*ex, v = M*ez
__device__ __forceinline__ void uv_cols(float phi, float th, float om,
                                        float u[3], float v[3])
{
    float sp, cp, st, ct, so, co;
    sincosf(phi, &sp, &cp);
    sincosf(th,  &st, &ct);
    sincosf(om,  &so, &co);
    float ax = ct * cp, ay = sp, az = -st * cp;
    u[0] = ax * co - ay * so;
    u[1] = ax * so + ay * co;
    u[2] = az;
    v[0] = st * co;
    v[1] = st * so;
    v[2] = ct;
}

// ---------------------------------------------------------------------------
// Phase 1: raw (S,C).  rows [0,8192) -> query side, [8192,16384) -> key side
// ---------------------------------------------------------------------------
__global__ void prep_kernel(const float* __restrict__ query,
                            const float* __restrict__ key)
{
    int row = blockIdx.x * blockDim.x + threadIdx.x;
    if (row >= 2 * NROWS_) return;

    bool isQ = row < NROWS_;
    int r = isQ ? row : row - NROWS_;

    // first 4 of the 64 features, 16B-aligned (row stride 256B)
    float4 xv = *(const float4*)((isQ ? query : key) + (size_t)r * D_);
    float xs[4] = {xv.x, xv.y, xv.z, xv.w};

    float S[NQ_], C[NQ_];
#pragma unroll
    for (int n = 0; n < NQ_; n++) {
        float t = tanhf(xs[n]);
        sincospif(t, &S[n], &C[n]);
    }

    if (isQ) {
        float out8[8];
#pragma unroll
        for (int n = 0; n < NQ_; n++) {
            out8[2 * n]     = 0.5f * S[n];
            out8[2 * n + 1] = 0.5f * C[n];
        }
        float* d = g_q + (size_t)r * 8;
        *(float4*)(d)     = *(const float4*)(out8);
        *(float4*)(d + 4) = *(const float4*)(out8 + 4);
    } else {
        int b = r >> 10;           // SK_ = 1024
        int s = r & (SK_ - 1);
#pragma unroll
        for (int n = 0; n < NQ_; n++) {
            g_k[((size_t)(b * 8 + 2 * n))     * SK_ + s] = S[n];
            g_k[((size_t)(b * 8 + 2 * n + 1)) * SK_ + s] = C[n];
        }
    }
}

// ---------------------------------------------------------------------------
// Phase 2: out[b][q][k] = 0.5 + 0.5 * prod_n (0.5 + q.(G k))
// Tile: 128 q x 128 k, 256 threads; thread owns 4 k-cols as packed pairs,
// iterates 16 q-rows.  G computed once per block (8+16 threads), applied to
// the register k-tile one time.
// ---------------------------------------------------------------------------
#define TQ 128
#define TK 128

__global__ __launch_bounds__(256) void pair_kernel(float* __restrict__ out,
                                                   const float* __restrict__ theta_q,
                                                   const float* __restrict__ theta_k)
{
    __shared__ __align__(16) float  sqd[TQ][16];       // duplicated q pairs
    __shared__ __align__(16) float4 skv[8][TK / 4];    // SoA raw k tile
    __shared__ float  su[2][NQ_][6];                   // u,v per side/qubit
    __shared__ __align__(8) float2 sGd[16];            // G entries, duplicated

    int b  = blockIdx.z;
    int q0 = blockIdx.y * TQ;
    int k0 = blockIdx.x * TK;
    int tid = threadIdx.x;

    // ---- block-scope G, stage A: u,v columns (8 threads) ----
    if (tid < 8) {
        int side = tid >> 2, n = tid & 3;
        const float* th = side ? theta_k : theta_q;
        float u[3], v[3];
        uv_cols(th[3 * n], th[3 * n + 1], th[3 * n + 2], u, v);
#pragma unroll
        for (int j = 0; j < 3; j++) {
            su[side][n][j]     = u[j];
            su[side][n][3 + j] = v[j];
        }
    }

    // ---- tile loads (independent of G) ----
    {
        int comp = tid >> 5, off = tid & 31;
        skv[comp][off] =
            *(const float4*)(g_k + ((size_t)(b * 8 + comp)) * SK_ + k0 + off * 4);
    }
#pragma unroll
    for (int i = tid; i < TQ * 8; i += 256) {
        int row = i >> 3, comp = i & 7;
        float v = g_q[(size_t)(b * SQ_ + q0 + row) * 8 + comp];
        *(float2*)&sqd[row][comp * 2] = make_float2(v, v);
    }
    __syncthreads();

    // ---- stage B: Gram entries (16 threads) ----
    if (tid < 16) {
        int n = tid >> 2, i = (tid >> 1) & 1, j = tid & 1;
        const float* a  = &su[0][n][3 * i];
        const float* bb = &su[1][n][3 * j];
        float g = a[0] * bb[0] + a[1] * bb[1] + a[2] * bb[2];
        sGd[n * 4 + i * 2 + j] = make_float2(g, g);
    }
    __syncthreads();

    int k4 = tid & 31;     // this thread's 4 consecutive k columns
    int qg = tid >> 5;     // q group: rows qg*16 .. qg*16+15

    // raw k tile -> apply G in registers (one-time, 32 packed ops)
    ulonglong2 kd[8];
#pragma unroll
    for (int j = 0; j < 8; j++)
        kd[j] = *(const ulonglong2*)&skv[j][k4];

#pragma unroll
    for (int n = 0; n < NQ_; n++) {
        unsigned long long g00 = *(const unsigned long long*)&sGd[n * 4 + 0];
        unsigned long long g01 = *(const unsigned long long*)&sGd[n * 4 + 1];
        unsigned long long g10 = *(const unsigned long long*)&sGd[n * 4 + 2];
        unsigned long long g11 = *(const unsigned long long*)&sGd[n * 4 + 3];
        ulonglong2 S = kd[2 * n], C = kd[2 * n + 1];
        kd[2 * n].x     = f2fma(g00, S.x, f2mul(g01, C.x));
        kd[2 * n].y     = f2fma(g00, S.y, f2mul(g01, C.y));
        kd[2 * n + 1].x = f2fma(g10, S.x, f2mul(g11, C.x));
        kd[2 * n + 1].y = f2fma(g10, S.y, f2mul(g11, C.y));
    }

    float* obase = out + ((size_t)(b * SQ_ + q0 + qg * 16) * SK_) + k0 + k4 * 4;

#pragma unroll
    for (int r = 0; r < 16; r++) {
        // 4 LDS.128 -> 8 packed q components (warp-uniform broadcast)
        unsigned long long qd[8];
        const ulonglong2* qrow = (const ulonglong2*)&sqd[qg * 16 + r][0];
#pragma unroll
        for (int j = 0; j < 4; j++) {
            ulonglong2 v = qrow[j];
            qd[2 * j]     = v.x;
            qd[2 * j + 1] = v.y;
        }

        unsigned long long t0[NQ_], t1[NQ_];
#pragma unroll
        for (int n = 0; n < NQ_; n++) {
            t0[n] = f2fma(qd[2 * n], kd[2 * n].x,
                    f2fma(qd[2 * n + 1], kd[2 * n + 1].x, HALF2_));
            t1[n] = f2fma(qd[2 * n], kd[2 * n].y,
                    f2fma(qd[2 * n + 1], kd[2 * n + 1].y, HALF2_));
        }
        unsigned long long p0 = f2mul(f2mul(t0[0], t0[1]), f2mul(t0[2], t0[3]));
        unsigned long long p1 = f2mul(f2mul(t1[0], t1[1]), f2mul(t1[2], t1[3]));
        p0 = f2fma(p0, HALF2_, HALF2_);
        p1 = f2fma(p1, HALF2_, HALF2_);

        asm volatile("st.global.v2.b64 [%0], {%1, %2};"
                     :: "l"(obase + (size_t)r * SK_), "l"(p0), "l"(p1)
                     : "memory");
    }
}

extern "C" void kernel_launch(void* const* d_in, const int* in_sizes, int n_in,
                              void* d_out, int out_size)
{
    const float* query   = (const float*)d_in[0];
    const float* key     = (const float*)d_in[1];
    const float* theta_q = (const float*)d_in[2];
    const float* theta_k = (const float*)d_in[3];
    float* out = (float*)d_out;

    prep_kernel<<<(2 * NROWS_ + 255) / 256, 256>>>(query, key);

    dim3 grid(SK_ / TK, SQ_ / TQ, B_);
    pair_kernel<<<grid, 256>>>(out, theta_q, theta_k);
}